// round 16
// baseline (speedup 1.0000x reference)
#include <cuda_runtime.h>

#define NB 4
#define LL 4096
#define KMAX 64
#define NCODES 256
#define QPB 64                 // queries per block
#define FULLM 0xffffffffu

__device__ __forceinline__ int pack8(float4 a, float4 c) {
    return (a.x > 0.f)        | ((a.y > 0.f) << 1) |
           ((a.z > 0.f) << 2) | ((a.w > 0.f) << 3) |
           ((c.x > 0.f) << 4) | ((c.y > 0.f) << 5) |
           ((c.z > 0.f) << 6) | ((c.w > 0.f) << 7);
}

__device__ __forceinline__ float cvt1(unsigned v) {
    return (v == 0xFFFFu) ? -1.0f : (float)v;
}

// ONE kernel, no global scratch, no inter-block deps. Block = (batch, 64-query
// chunk). Builds the full 256-row table for its batch in smem (u16), then
// emits its 64 queries. 41.5KB smem -> 2+ blocks/SM overlap the serial scans.
__global__ void __launch_bounds__(256)
k_all(const float* __restrict__ key_up,
      const float* __restrict__ query_up,
      float* __restrict__ out) {
    __shared__ unsigned char  sc  [LL];             //  4 KB key codes
    __shared__ unsigned short rows[NCODES * KMAX];  // 32 KB result table
    __shared__ unsigned short hist[8 * NCODES];     //  4 KB per-warp counts
    __shared__ unsigned short scnt[NCODES];         // 512 B totals
    __shared__ unsigned char  qc  [QPB];            // query codes
    __shared__ int oflow;

    int tid  = threadIdx.x;
    int warp = tid >> 5;
    int lane = tid & 31;
    int b    = blockIdx.x >> 6;                     // batch
    int qbase= b * LL + (blockIdx.x & 63) * QPB;    // first query

    // ---- query codes (64 threads, independent loads) ----
    if (tid < QPB) {
        const float4* qp = reinterpret_cast<const float4*>(query_up)
                           + (size_t)(qbase + tid) * 2;
        float4 q0 = qp[0], q1 = qp[1];
        qc[tid] = (unsigned char)pack8(q0, q1);
    }

    // ---- init rows=0xFFFF, hist/scnt=0 ----
    {
        uint4 ff = make_uint4(FULLM, FULLM, FULLM, FULLM);
        uint4* rp = reinterpret_cast<uint4*>(rows);
        #pragma unroll
        for (int i = 0; i < 8; i++) rp[tid + i * 256] = ff;
        int* hp = reinterpret_cast<int*>(hist);     // hist + scnt contiguous? no:
        #pragma unroll                              // zero hist (1024 ints)
        for (int i = 0; i < 4; i++) hp[tid + i * 256] = 0;
        if (tid < 128) reinterpret_cast<int*>(scnt)[tid] = 0;
        if (tid == 0) oflow = 0;
    }

    // ---- pack key codes to smem (coalesced, full MLP, NOT in a serial chain) ----
    const float4* kb = reinterpret_cast<const float4*>(key_up + (size_t)b * LL * 8);
    #pragma unroll
    for (int i = 0; i < 16; i++) {
        int j = tid + i * 256;
        sc[j] = (unsigned char)pack8(kb[j * 2], kb[j * 2 + 1]);
    }
    __syncthreads();

    // ---- per-warp match scan over smem codes (warp w: keys [w*512,+512)) ----
    unsigned lt = (1u << lane) - 1u;
    int myc[16], mypos[16];                         // mypos = warp-local index
    #pragma unroll
    for (int k = 0; k < 16; k++) {
        int c = sc[warp * 512 + k * 32 + lane];
        unsigned mask = __match_any_sync(FULLM, c);
        int before = (int)hist[warp * NCODES + c];
        myc[k]   = c;
        mypos[k] = before + __popc(mask & lt);
        __syncwarp();
        if ((mask & lt) == 0)                       // group leader
            hist[warp * NCODES + c] = (unsigned short)(before + __popc(mask));
        __syncwarp();
    }
    __syncthreads();

    // ---- exclusive prefix across the 8 warp histograms ----
    if (tid < NCODES) {
        int tot = 0;
        #pragma unroll
        for (int w = 0; w < 8; w++) {
            int t = hist[w * NCODES + tid];
            hist[w * NCODES + tid] = (unsigned short)tot;   // becomes base
            tot += t;
        }
        scnt[tid] = (unsigned short)tot;
        if (tot > KMAX) oflow = 1;
    }
    __syncthreads();

    // ---- write rows: pos = (64-n) + warp_base + warp_local_index ----
    #pragma unroll
    for (int k = 0; k < 16; k++) {
        int c = myc[k];
        int n = (int)scnt[c];
        if (n <= KMAX) {
            int pos = (KMAX - n) + (int)hist[warp * NCODES + c] + mypos[k];
            rows[c * KMAX + pos] = (unsigned short)(warp * 512 + k * 32 + lane);
        }
    }

    // ---- overflow fallback (n>64: stat. impossible, guarded; uniform branch) ----
    if (oflow) {
        __syncthreads();
        if (warp == 0) {
            for (int c = 0; c < NCODES; c++) {
                if ((int)scnt[c] > KMAX) {
                    int m = 0;
                    for (int r = 0; r < 32 && m < KMAX; r++) {
                        uchar4 v = reinterpret_cast<const uchar4*>(sc)[r * 32 + lane];
                        unsigned m0 = __ballot_sync(FULLM, v.x == c);
                        unsigned m1 = __ballot_sync(FULLM, v.y == c);
                        unsigned m2 = __ballot_sync(FULLM, v.z == c);
                        unsigned m3 = __ballot_sync(FULLM, v.w == c);
                        int p = m + __popc(m0 & lt) + __popc(m1 & lt)
                                  + __popc(m2 & lt) + __popc(m3 & lt);
                        int j0 = (r * 32 + lane) * 4;
                        if (v.x == c) { if (p < KMAX) rows[c*KMAX+p] = (unsigned short)j0;     p++; }
                        if (v.y == c) { if (p < KMAX) rows[c*KMAX+p] = (unsigned short)(j0+1); p++; }
                        if (v.z == c) { if (p < KMAX) rows[c*KMAX+p] = (unsigned short)(j0+2); p++; }
                        if (v.w == c) { if (p < KMAX) rows[c*KMAX+p] = (unsigned short)(j0+3); p++; }
                        m += __popc(m0) + __popc(m1) + __popc(m2) + __popc(m3);
                    }
                }
            }
        }
    }
    __syncthreads();

    // ---- emit: 4 threads per query; u16 -> float inline; 2KB/warp stores ----
    {
        int q    = tid >> 2;                        // 0..63
        int part = tid & 3;                         // 16 entries each
        int c    = (int)qc[q];
        const uint4* rw = reinterpret_cast<const uint4*>(
                              rows + c * KMAX + part * 16);
        uint4 r0 = rw[0];
        uint4 r1 = rw[1];
        unsigned wds[8] = {r0.x, r0.y, r0.z, r0.w, r1.x, r1.y, r1.z, r1.w};
        float4* dst = reinterpret_cast<float4*>(
                          out + (size_t)(qbase + q) * KMAX + part * 16);
        #pragma unroll
        for (int i = 0; i < 4; i++) {
            float4 f;
            f.x = cvt1(wds[i*2]   & 0xFFFFu);
            f.y = cvt1(wds[i*2]   >> 16);
            f.z = cvt1(wds[i*2+1] & 0xFFFFu);
            f.w = cvt1(wds[i*2+1] >> 16);
            dst[i] = f;
        }
    }
}

extern "C" void kernel_launch(void* const* d_in, const int* in_sizes, int n_in,
                              void* d_out, int out_size) {
    // Identify inputs by element count (robust to metadata ordering).
    const float* query_up = nullptr;
    const float* key_up   = nullptr;
    for (int i = 0; i < n_in; i++) {
        if (in_sizes[i] == NB * LL * 8) {
            if (!query_up)      query_up = (const float*)d_in[i];
            else if (!key_up)   key_up   = (const float*)d_in[i];
        }
    }
    if (!query_up || !key_up) {
        query_up = (const float*)d_in[0];
        key_up   = (const float*)d_in[1];
    }
    float* out = (float*)d_out;

    k_all<<<NB * 64, 256>>>(key_up, query_up, out);   // 256 blocks, 1 node
}

// round 17
// speedup vs baseline: 1.7464x; 1.7464x over previous
#include <cuda_runtime.h>

#define NB 4
#define LL 4096
#define ND 8
#define KMAX 64
#define NCODES 256
#define BIGV 65535

// Scratch (no allocations). g_cnt zero-initialized; reset by k_rank each run
// (exactly one warp owns each counter) -> deterministic across graph replays.
__device__ float          g_rows  [NB * NCODES * KMAX];  // 256 KB
__device__ int            g_cnt   [NB * NCODES];         // 4 KB
__device__ unsigned short g_tmp   [NB * NCODES * KMAX];  // 128 KB buckets
__device__ unsigned char  g_codes [NB * LL];             // 16 KB key codes
__device__ unsigned char  g_qcodes[NB * LL];             // 16 KB query codes

__device__ __forceinline__ int pack8(float4 a, float4 c) {
    return (a.x > 0.f)        | ((a.y > 0.f) << 1) |
           ((a.z > 0.f) << 2) | ((a.w > 0.f) << 3) |
           ((c.x > 0.f) << 4) | ((c.y > 0.f) << 5) |
           ((c.z > 0.f) << 6) | ((c.w > 0.f) << 7);
}

// K1: 32K threads. Blocks 0..63: scatter keys into (batch,code) buckets.
// Blocks 64..127: pack query codes into g_qcodes.
__global__ void k_prep(const float* __restrict__ key_up,
                       const float* __restrict__ query_up) {
    int tid = threadIdx.x;
    if (blockIdx.x < 64) {
        int t = blockIdx.x * 256 + tid;                  // key id 0..16383
        const float4* p = reinterpret_cast<const float4*>(key_up) + t * 2;
        int code = pack8(p[0], p[1]);
        g_codes[t] = (unsigned char)code;
        int cidx = ((t >> 12) << 8) | code;
        int pos = atomicAdd(&g_cnt[cidx], 1);
        if (pos < KMAX) g_tmp[cidx * KMAX + pos] = (unsigned short)(t & (LL - 1));
    } else {
        int t = (blockIdx.x - 64) * 256 + tid;           // query id 0..16383
        const float4* p = reinterpret_cast<const float4*>(query_up) + t * 2;
        g_qcodes[t] = (unsigned char)pack8(p[0], p[1]);
    }
}

// K2: one warp per (batch,code). Rank-sort <=64 bucket entries (distinct j,
// arbitrary arrival order) into the padded ascending row; reset the counter.
__global__ void k_rank() {
    int gw   = (blockIdx.x * blockDim.x + threadIdx.x) >> 5;  // 0..1023 = cidx
    int lane = threadIdx.x & 31;
    int n    = g_cnt[gw];
    float* row = g_rows + gw * KMAX;

    if (n <= KMAX) {
        int v0 = (lane      < n) ? (int)g_tmp[gw * KMAX + lane]      : BIGV;
        int v1 = (lane + 32 < n) ? (int)g_tmp[gw * KMAX + lane + 32] : BIGV;
        int r0 = 0, r1 = 0;
        #pragma unroll
        for (int k = 0; k < 32; k++) {
            int u0 = __shfl_sync(0xffffffffu, v0, k);
            int u1 = __shfl_sync(0xffffffffu, v1, k);
            r0 += (u0 < v0) + (u1 < v0);
            r1 += (u0 < v1) + (u1 < v1);
        }
        int pad = KMAX - n;              // disjoint targets, no syncs needed
        if (lane      < pad) row[lane]      = -1.0f;
        if (lane + 32 < pad) row[lane + 32] = -1.0f;
        if (v0 != BIGV) row[pad + r0] = (float)v0;
        if (v1 != BIGV) row[pad + r1] = (float)v1;
    } else {
        // >64 matches (stat. impossible for sign codes, guarded): stable scan.
        int b = gw >> 8, c = gw & 255;
        const uchar4* cc = reinterpret_cast<const uchar4*>(g_codes + b * LL);
        unsigned lt = (1u << lane) - 1u;
        int m = 0;
        for (int r = 0; r < 32 && m < KMAX; r++) {
            uchar4 v = cc[r * 32 + lane];
            unsigned m0 = __ballot_sync(0xffffffffu, v.x == c);
            unsigned m1 = __ballot_sync(0xffffffffu, v.y == c);
            unsigned m2 = __ballot_sync(0xffffffffu, v.z == c);
            unsigned m3 = __ballot_sync(0xffffffffu, v.w == c);
            int p = m + __popc(m0 & lt) + __popc(m1 & lt)
                      + __popc(m2 & lt) + __popc(m3 & lt);
            int j0 = (r * 32 + lane) * 4;
            if (v.x == c) { if (p < KMAX) row[p] = (float)j0;       p++; }
            if (v.y == c) { if (p < KMAX) row[p] = (float)(j0 + 1); p++; }
            if (v.z == c) { if (p < KMAX) row[p] = (float)(j0 + 2); p++; }
            if (v.w == c) { if (p < KMAX) row[p] = (float)(j0 + 3); p++; }
            m += __popc(m0) + __popc(m1) + __popc(m2) + __popc(m3);
        }
    }
    if (lane == 0) g_cnt[gw] = 0;        // self-reset for next graph replay
}

// K3: flat streaming copy, one output float4 per thread (262,144 threads).
// code byte is L1-broadcast (16 threads share), row float4 from L2-hot g_rows,
// store fully coalesced to DRAM.
__global__ void k_emit(float* __restrict__ out) {
    int i  = blockIdx.x * blockDim.x + threadIdx.x;      // 0..262143
    int qi = i >> 4;                                     // query id
    int k  = i & 15;                                     // float4 within row
    int b  = qi >> 12;
    int code = (int)g_qcodes[qi];
    reinterpret_cast<float4*>(out)[i] =
        reinterpret_cast<const float4*>(g_rows)[(((b << 8) + code) << 4) + k];
}

extern "C" void kernel_launch(void* const* d_in, const int* in_sizes, int n_in,
                              void* d_out, int out_size) {
    // Identify inputs by element count (robust to metadata ordering).
    const float* query_up = nullptr;
    const float* key_up   = nullptr;
    for (int i = 0; i < n_in; i++) {
        if (in_sizes[i] == NB * LL * ND) {
            if (!query_up)      query_up = (const float*)d_in[i];
            else if (!key_up)   key_up   = (const float*)d_in[i];
        }
    }
    if (!query_up || !key_up) {
        query_up = (const float*)d_in[0];
        key_up   = (const float*)d_in[1];
    }
    float* out = (float*)d_out;

    k_prep<<<128, 256>>>(key_up, query_up);  // 32K threads
    k_rank<<<256, 128>>>();                  // 1024 warps, 256 blocks
    k_emit<<<1024, 256>>>(out);              // 262,144 threads, 1 float4 each
}